// round 7
// baseline (speedup 1.0000x reference)
#include <cuda_runtime.h>
#include <cuda_bf16.h>

// Problem constants
#define DD 128            // feature dim D == H
#define TM 64             // rows per CTA tile
#define NTHREADS 256
#define N_MESH  40962
#define N_GRIDN 200000
#define N_EDGES 600000

// ---------------------------------------------------------------------------
// Scratch buffers (static __device__ arrays — allocation-free per the rules)
// ---------------------------------------------------------------------------
__device__ __align__(16) float g_Pmesh[(size_t)N_MESH  * DD];   //  21.0 MB
__device__ __align__(16) float g_Pgrid[(size_t)N_GRIDN * DD];   // 102.4 MB
__device__ __align__(16) float g_efeat[(size_t)N_EDGES * DD];   // 307.2 MB

// ---------------------------------------------------------------------------
// Helpers
// ---------------------------------------------------------------------------
__device__ __forceinline__ float4 ld4(const float* p) {
    return *reinterpret_cast<const float4*>(p);
}
__device__ __forceinline__ void st4(float* p, float4 v) {
    *reinterpret_cast<float4*>(p) = v;
}
__device__ __forceinline__ float warp_allred(float v) {
    #pragma unroll
    for (int o = 16; o > 0; o >>= 1) v += __shfl_xor_sync(0xffffffffu, v, o);
    return v;
}
__device__ __forceinline__ float silu_f(float x) {
    return x / (1.0f + __expf(-x));
}

// Load a TM x 128 A-tile into shared memory (float4, fully coalesced).
__device__ __forceinline__ void load_A(float* As, const float* gA, int rows_valid) {
    #pragma unroll
    for (int t = threadIdx.x; t < TM * 32; t += NTHREADS) {
        int r = t >> 5;
        int c = (t & 31) * 4;
        float4 v = make_float4(0.f, 0.f, 0.f, 0.f);
        if (r < rows_valid) v = ld4(gA + (size_t)r * DD + c);
        st4(As + r * DD + c, v);
    }
}

// Load a 128 x 128 weight tile into shared memory.
__device__ __forceinline__ void load_W(float* Wsm, const float* gW) {
    #pragma unroll
    for (int t = threadIdx.x; t < DD * 32; t += NTHREADS) {
        int r = t >> 5;
        int c = (t & 31) * 4;
        st4(Wsm + r * DD + c, ld4(gW + (size_t)r * DD + c));
    }
}

// Register-tiled GEMM: acc[i][c] += sum_k As[rg*8+i][k] * Wsm[k][cg*4+c]
// 256 threads: rg = tid>>5 (8 row groups of 8 rows), cg = tid&31 (32 col
// groups of 4 cols). A reads are warp-broadcast, W reads are conflict-free
// float4 across the 512B row.
__device__ __forceinline__ void gemm_tile(const float* __restrict__ As,
                                          const float* __restrict__ Wsm,
                                          int rg, int cg, float acc[8][4]) {
    const float* arow = As + rg * 8 * DD;
    const float* wcol = Wsm + cg * 4;
    #pragma unroll 2
    for (int k = 0; k < DD; k += 4) {
        float4 w0 = ld4(wcol + (k + 0) * DD);
        float4 w1 = ld4(wcol + (k + 1) * DD);
        float4 w2 = ld4(wcol + (k + 2) * DD);
        float4 w3 = ld4(wcol + (k + 3) * DD);
        #pragma unroll
        for (int i = 0; i < 8; i++) {
            float4 a = ld4(arow + i * DD + k);
            acc[i][0] += a.x * w0.x; acc[i][0] += a.y * w1.x;
            acc[i][0] += a.z * w2.x; acc[i][0] += a.w * w3.x;
            acc[i][1] += a.x * w0.y; acc[i][1] += a.y * w1.y;
            acc[i][1] += a.z * w2.y; acc[i][1] += a.w * w3.y;
            acc[i][2] += a.x * w0.z; acc[i][2] += a.y * w1.z;
            acc[i][2] += a.z * w2.z; acc[i][2] += a.w * w3.z;
            acc[i][3] += a.x * w0.w; acc[i][3] += a.y * w1.w;
            acc[i][3] += a.z * w2.w; acc[i][3] += a.w * w3.w;
        }
    }
}

// ---------------------------------------------------------------------------
// Kernel 1/2: C[M,128] = A[M,128] @ W[128,128]   (no bias)
// ---------------------------------------------------------------------------
__global__ void __launch_bounds__(NTHREADS, 2)
proj_kernel(const float* __restrict__ A, const float* __restrict__ W,
            float* __restrict__ C, int M) {
    extern __shared__ float sm[];
    float* As  = sm;
    float* Wsm = sm + TM * DD;

    int m0 = blockIdx.x * TM;
    int rv = M - m0; if (rv > TM) rv = TM;

    load_A(As, A + (size_t)m0 * DD, rv);
    load_W(Wsm, W);
    __syncthreads();

    int cg = threadIdx.x & 31, rg = threadIdx.x >> 5;
    float acc[8][4] = {};
    gemm_tile(As, Wsm, rg, cg, acc);

    #pragma unroll
    for (int i = 0; i < 8; i++) {
        int r = rg * 8 + i;
        if (r < rv) {
            float4 v = make_float4(acc[i][0], acc[i][1], acc[i][2], acc[i][3]);
            st4(C + (size_t)(m0 + r) * DD + cg * 4, v);
        }
    }
}

// ---------------------------------------------------------------------------
// Kernel 3: edge TMLP
//   h     = silu(m2g@We + Pmesh[src] + Pgrid[dst] + b0)
//   efeat = LayerNorm(h@W1e + b1e; ge, be)          -> g_efeat
// ---------------------------------------------------------------------------
__global__ void __launch_bounds__(NTHREADS, 2)
edge_kernel(const float* __restrict__ m2g,
            const int* __restrict__ src, const int* __restrict__ dst,
            const float* __restrict__ We, const float* __restrict__ W1e,
            const float* __restrict__ b0, const float* __restrict__ b1e,
            const float* __restrict__ ge, const float* __restrict__ be) {
    extern __shared__ float sm[];
    float* As  = sm;
    float* Wsm = sm + TM * DD;

    int e0 = blockIdx.x * TM;
    load_A(As, m2g + (size_t)e0 * DD, TM);
    load_W(Wsm, We);
    __syncthreads();

    int cg = threadIdx.x & 31, rg = threadIdx.x >> 5;
    float acc[8][4] = {};
    gemm_tile(As, Wsm, rg, cg, acc);

    // epilogue 1: gathers + bias + silu (no shared-mem access)
    float4 b0v = ld4(b0 + cg * 4);
    #pragma unroll
    for (int i = 0; i < 8; i++) {
        int e = e0 + rg * 8 + i;
        int s = __ldg(src + e);
        int d = __ldg(dst + e);
        float4 pm = ld4(g_Pmesh + (size_t)s * DD + cg * 4);
        float4 pg = ld4(g_Pgrid + (size_t)d * DD + cg * 4);
        acc[i][0] = silu_f(acc[i][0] + pm.x + pg.x + b0v.x);
        acc[i][1] = silu_f(acc[i][1] + pm.y + pg.y + b0v.y);
        acc[i][2] = silu_f(acc[i][2] + pm.z + pg.z + b0v.z);
        acc[i][3] = silu_f(acc[i][3] + pm.w + pg.w + b0v.w);
    }
    __syncthreads();            // everyone done reading As / Wsm

    #pragma unroll
    for (int i = 0; i < 8; i++)
        st4(As + (rg * 8 + i) * DD + cg * 4,
            make_float4(acc[i][0], acc[i][1], acc[i][2], acc[i][3]));
    load_W(Wsm, W1e);
    __syncthreads();

    float acc2[8][4] = {};
    gemm_tile(As, Wsm, rg, cg, acc2);

    float4 b1v = ld4(b1e + cg * 4);
    float4 gv  = ld4(ge  + cg * 4);
    float4 bv  = ld4(be  + cg * 4);
    #pragma unroll
    for (int i = 0; i < 8; i++) {
        float v0 = acc2[i][0] + b1v.x;
        float v1 = acc2[i][1] + b1v.y;
        float v2 = acc2[i][2] + b1v.z;
        float v3 = acc2[i][3] + b1v.w;
        float mu = warp_allred(v0 + v1 + v2 + v3) * 0.0078125f;
        v0 -= mu; v1 -= mu; v2 -= mu; v3 -= mu;
        float var = warp_allred(v0*v0 + v1*v1 + v2*v2 + v3*v3) * 0.0078125f;
        float rstd = rsqrtf(var + 1e-5f);
        float4 o;
        o.x = v0 * rstd * gv.x + bv.x;
        o.y = v1 * rstd * gv.y + bv.y;
        o.z = v2 * rstd * gv.z + bv.z;
        o.w = v3 * rstd * gv.w + bv.w;
        st4(g_efeat + (size_t)(e0 + rg * 8 + i) * DD + cg * 4, o);
    }
}

// ---------------------------------------------------------------------------
// Kernel 4: node MLP
//   agg = segment_sum(efeat, dst)      (dst sorted -> binary-searched ranges)
//   hn  = silu([grid, agg] @ Wn0 + bn0)
//   out = LayerNorm(hn@Wn1 + bn1; gn, bn) + grid
// ---------------------------------------------------------------------------
__global__ void __launch_bounds__(NTHREADS, 2)
node_kernel(const float* __restrict__ grid, const int* __restrict__ dst,
            const float* __restrict__ Wn0, const float* __restrict__ bn0,
            const float* __restrict__ Wn1, const float* __restrict__ bn1,
            const float* __restrict__ gn, const float* __restrict__ bn,
            float* __restrict__ out) {
    extern __shared__ float sm[];
    float* As  = sm;
    float* Wsm = sm + TM * DD;
    int* sLo = (int*)(sm + TM * DD + DD * DD);
    int* sHi = sLo + TM;

    int n0 = blockIdx.x * TM;

    // per-node edge ranges via lower_bound on the sorted dst index
    if (threadIdx.x < TM) {
        int n = n0 + (int)threadIdx.x;
        int lo = 0, hi = N_EDGES;
        while (lo < hi) { int m = (lo + hi) >> 1; if (dst[m] <  n) lo = m + 1; else hi = m; }
        sLo[threadIdx.x] = lo;
        int lo2 = lo, hi2 = N_EDGES;
        while (lo2 < hi2) { int m = (lo2 + hi2) >> 1; if (dst[m] <= n) lo2 = m + 1; else hi2 = m; }
        sHi[threadIdx.x] = lo2;
    }

    // pass 1: grid half of the concat, Wn0 rows [0,128)
    load_A(As, grid + (size_t)n0 * DD, TM);
    load_W(Wsm, Wn0);
    __syncthreads();

    int cg = threadIdx.x & 31, rg = threadIdx.x >> 5;
    float acc[8][4] = {};
    gemm_tile(As, Wsm, rg, cg, acc);
    __syncthreads();

    // pass 2: aggregate efeat into As, Wn0 rows [128,256)
    #pragma unroll
    for (int i = 0; i < 8; i++) {
        int r = rg * 8 + i;
        int lo = sLo[r], hi = sHi[r];
        float4 s = make_float4(0.f, 0.f, 0.f, 0.f);
        for (int e = lo; e < hi; e++) {
            float4 v = ld4(g_efeat + (size_t)e * DD + cg * 4);
            s.x += v.x; s.y += v.y; s.z += v.z; s.w += v.w;
        }
        st4(As + r * DD + cg * 4, s);
    }
    load_W(Wsm, Wn0 + (size_t)DD * DD);
    __syncthreads();

    gemm_tile(As, Wsm, rg, cg, acc);   // accumulate onto grid-half partials

    float4 bn0v = ld4(bn0 + cg * 4);
    #pragma unroll
    for (int i = 0; i < 8; i++) {
        acc[i][0] = silu_f(acc[i][0] + bn0v.x);
        acc[i][1] = silu_f(acc[i][1] + bn0v.y);
        acc[i][2] = silu_f(acc[i][2] + bn0v.z);
        acc[i][3] = silu_f(acc[i][3] + bn0v.w);
    }
    __syncthreads();

    #pragma unroll
    for (int i = 0; i < 8; i++)
        st4(As + (rg * 8 + i) * DD + cg * 4,
            make_float4(acc[i][0], acc[i][1], acc[i][2], acc[i][3]));
    load_W(Wsm, Wn1);
    __syncthreads();

    float acc2[8][4] = {};
    gemm_tile(As, Wsm, rg, cg, acc2);

    float4 b1v = ld4(bn1 + cg * 4);
    float4 gv  = ld4(gn  + cg * 4);
    float4 bv  = ld4(bn  + cg * 4);
    #pragma unroll
    for (int i = 0; i < 8; i++) {
        int n = n0 + rg * 8 + i;
        float v0 = acc2[i][0] + b1v.x;
        float v1 = acc2[i][1] + b1v.y;
        float v2 = acc2[i][2] + b1v.z;
        float v3 = acc2[i][3] + b1v.w;
        float mu = warp_allred(v0 + v1 + v2 + v3) * 0.0078125f;
        v0 -= mu; v1 -= mu; v2 -= mu; v3 -= mu;
        float var = warp_allred(v0*v0 + v1*v1 + v2*v2 + v3*v3) * 0.0078125f;
        float rstd = rsqrtf(var + 1e-5f);
        float4 gr = ld4(grid + (size_t)n * DD + cg * 4);
        float4 o;
        o.x = v0 * rstd * gv.x + bv.x + gr.x;
        o.y = v1 * rstd * gv.y + bv.y + gr.y;
        o.z = v2 * rstd * gv.z + bv.z + gr.z;
        o.w = v3 * rstd * gv.w + bv.w + gr.w;
        st4(out + (size_t)n * DD + cg * 4, o);
    }
}

// ---------------------------------------------------------------------------
// Launch
// ---------------------------------------------------------------------------
extern "C" void kernel_launch(void* const* d_in, const int* in_sizes, int n_in,
                              void* d_out, int out_size) {
    (void)in_sizes; (void)n_in; (void)out_size;

    const float* m2g  = (const float*)d_in[0];
    const float* grid = (const float*)d_in[1];
    const float* mesh = (const float*)d_in[2];
    const int*   src  = (const int*)  d_in[3];
    const int*   dst  = (const int*)  d_in[4];
    const float* We   = (const float*)d_in[5];
    const float* Ws   = (const float*)d_in[6];
    const float* Wd   = (const float*)d_in[7];
    const float* b0   = (const float*)d_in[8];
    const float* W1e  = (const float*)d_in[9];
    const float* b1e  = (const float*)d_in[10];
    const float* ge   = (const float*)d_in[11];
    const float* be   = (const float*)d_in[12];
    const float* Wn0  = (const float*)d_in[13];
    const float* bn0  = (const float*)d_in[14];
    const float* Wn1  = (const float*)d_in[15];
    const float* bn1  = (const float*)d_in[16];
    const float* gn   = (const float*)d_in[17];
    const float* bn   = (const float*)d_in[18];
    float* out = (float*)d_out;

    const int SMEM = (TM * DD + DD * DD) * (int)sizeof(float) + 2 * TM * (int)sizeof(int);

    cudaFuncSetAttribute(proj_kernel, cudaFuncAttributeMaxDynamicSharedMemorySize, SMEM);
    cudaFuncSetAttribute(edge_kernel, cudaFuncAttributeMaxDynamicSharedMemorySize, SMEM);
    cudaFuncSetAttribute(node_kernel, cudaFuncAttributeMaxDynamicSharedMemorySize, SMEM);

    void *pm = nullptr, *pg = nullptr;
    cudaGetSymbolAddress(&pm, g_Pmesh);
    cudaGetSymbolAddress(&pg, g_Pgrid);

    proj_kernel<<<(N_MESH + TM - 1) / TM, NTHREADS, SMEM>>>(mesh, Ws, (float*)pm, N_MESH);
    proj_kernel<<<N_GRIDN / TM,            NTHREADS, SMEM>>>(grid, Wd, (float*)pg, N_GRIDN);
    edge_kernel<<<N_EDGES / TM, NTHREADS, SMEM>>>(m2g, src, dst, We, W1e, b0, b1e, ge, be);
    node_kernel<<<N_GRIDN / TM, NTHREADS, SMEM>>>(grid, dst, Wn0, bn0, Wn1, bn1, gn, bn, out);
}

// round 8
// speedup vs baseline: 1.0014x; 1.0014x over previous
#include <cuda_runtime.h>
#include <cuda_bf16.h>

// Problem constants
#define DD 128            // feature dim D == H
#define TM 64             // rows per CTA tile
#define NTHREADS 256
#define N_MESH  40962
#define N_GRIDN 200000
#define N_EDGES 600000

// ---------------------------------------------------------------------------
// Scratch buffers (static __device__ arrays — allocation-free per the rules)
// ---------------------------------------------------------------------------
__device__ __align__(16) float g_Pmesh[(size_t)N_MESH  * DD];   //  21.0 MB
__device__ __align__(16) float g_Pgrid[(size_t)N_GRIDN * DD];   // 102.4 MB
__device__ __align__(16) float g_efeat[(size_t)N_EDGES * DD];   // 307.2 MB

// ---------------------------------------------------------------------------
// Helpers
// ---------------------------------------------------------------------------
__device__ __forceinline__ float4 ld4(const float* p) {
    return *reinterpret_cast<const float4*>(p);
}
__device__ __forceinline__ void st4(float* p, float4 v) {
    *reinterpret_cast<float4*>(p) = v;
}
__device__ __forceinline__ float warp_allred(float v) {
    #pragma unroll
    for (int o = 16; o > 0; o >>= 1) v += __shfl_xor_sync(0xffffffffu, v, o);
    return v;
}
__device__ __forceinline__ float silu_f(float x) {
    return x / (1.0f + __expf(-x));
}

// Load a TM x 128 A-tile into shared memory (float4, fully coalesced).
__device__ __forceinline__ void load_A(float* As, const float* gA, int rows_valid) {
    #pragma unroll
    for (int t = threadIdx.x; t < TM * 32; t += NTHREADS) {
        int r = t >> 5;
        int c = (t & 31) * 4;
        float4 v = make_float4(0.f, 0.f, 0.f, 0.f);
        if (r < rows_valid) v = ld4(gA + (size_t)r * DD + c);
        st4(As + r * DD + c, v);
    }
}

// Load a 128 x 128 weight tile into shared memory.
__device__ __forceinline__ void load_W(float* Wsm, const float* gW) {
    #pragma unroll
    for (int t = threadIdx.x; t < DD * 32; t += NTHREADS) {
        int r = t >> 5;
        int c = (t & 31) * 4;
        st4(Wsm + r * DD + c, ld4(gW + (size_t)r * DD + c));
    }
}

// Register-tiled GEMM: acc[i][c] += sum_k As[rg*8+i][k] * Wsm[k][cg*4+c]
// 256 threads: rg = tid>>5 (8 row groups of 8 rows), cg = tid&31 (32 col
// groups of 4 cols). A reads are warp-broadcast, W reads are conflict-free
// float4 across the 512B row.
__device__ __forceinline__ void gemm_tile(const float* __restrict__ As,
                                          const float* __restrict__ Wsm,
                                          int rg, int cg, float acc[8][4]) {
    const float* arow = As + rg * 8 * DD;
    const float* wcol = Wsm + cg * 4;
    #pragma unroll 2
    for (int k = 0; k < DD; k += 4) {
        float4 w0 = ld4(wcol + (k + 0) * DD);
        float4 w1 = ld4(wcol + (k + 1) * DD);
        float4 w2 = ld4(wcol + (k + 2) * DD);
        float4 w3 = ld4(wcol + (k + 3) * DD);
        #pragma unroll
        for (int i = 0; i < 8; i++) {
            float4 a = ld4(arow + i * DD + k);
            acc[i][0] += a.x * w0.x; acc[i][0] += a.y * w1.x;
            acc[i][0] += a.z * w2.x; acc[i][0] += a.w * w3.x;
            acc[i][1] += a.x * w0.y; acc[i][1] += a.y * w1.y;
            acc[i][1] += a.z * w2.y; acc[i][1] += a.w * w3.y;
            acc[i][2] += a.x * w0.z; acc[i][2] += a.y * w1.z;
            acc[i][2] += a.z * w2.z; acc[i][2] += a.w * w3.z;
            acc[i][3] += a.x * w0.w; acc[i][3] += a.y * w1.w;
            acc[i][3] += a.z * w2.w; acc[i][3] += a.w * w3.w;
        }
    }
}

// ---------------------------------------------------------------------------
// Kernel 1/2: C[M,128] = A[M,128] @ W[128,128]   (no bias)
// ---------------------------------------------------------------------------
__global__ void __launch_bounds__(NTHREADS, 2)
proj_kernel(const float* __restrict__ A, const float* __restrict__ W,
            float* __restrict__ C, int M) {
    extern __shared__ float sm[];
    float* As  = sm;
    float* Wsm = sm + TM * DD;

    int m0 = blockIdx.x * TM;
    int rv = M - m0; if (rv > TM) rv = TM;

    load_A(As, A + (size_t)m0 * DD, rv);
    load_W(Wsm, W);
    __syncthreads();

    int cg = threadIdx.x & 31, rg = threadIdx.x >> 5;
    float acc[8][4] = {};
    gemm_tile(As, Wsm, rg, cg, acc);

    #pragma unroll
    for (int i = 0; i < 8; i++) {
        int r = rg * 8 + i;
        if (r < rv) {
            float4 v = make_float4(acc[i][0], acc[i][1], acc[i][2], acc[i][3]);
            st4(C + (size_t)(m0 + r) * DD + cg * 4, v);
        }
    }
}

// ---------------------------------------------------------------------------
// Kernel 3: edge TMLP
//   h     = silu(m2g@We + Pmesh[src] + Pgrid[dst] + b0)
//   efeat = LayerNorm(h@W1e + b1e; ge, be)          -> g_efeat
// ---------------------------------------------------------------------------
__global__ void __launch_bounds__(NTHREADS, 2)
edge_kernel(const float* __restrict__ m2g,
            const int* __restrict__ src, const int* __restrict__ dst,
            const float* __restrict__ We, const float* __restrict__ W1e,
            const float* __restrict__ b0, const float* __restrict__ b1e,
            const float* __restrict__ ge, const float* __restrict__ be) {
    extern __shared__ float sm[];
    float* As  = sm;
    float* Wsm = sm + TM * DD;

    int e0 = blockIdx.x * TM;
    load_A(As, m2g + (size_t)e0 * DD, TM);
    load_W(Wsm, We);
    __syncthreads();

    int cg = threadIdx.x & 31, rg = threadIdx.x >> 5;
    float acc[8][4] = {};
    gemm_tile(As, Wsm, rg, cg, acc);

    // epilogue 1: gathers + bias + silu (no shared-mem access)
    float4 b0v = ld4(b0 + cg * 4);
    #pragma unroll
    for (int i = 0; i < 8; i++) {
        int e = e0 + rg * 8 + i;
        int s = __ldg(src + e);
        int d = __ldg(dst + e);
        float4 pm = ld4(g_Pmesh + (size_t)s * DD + cg * 4);
        float4 pg = ld4(g_Pgrid + (size_t)d * DD + cg * 4);
        acc[i][0] = silu_f(acc[i][0] + pm.x + pg.x + b0v.x);
        acc[i][1] = silu_f(acc[i][1] + pm.y + pg.y + b0v.y);
        acc[i][2] = silu_f(acc[i][2] + pm.z + pg.z + b0v.z);
        acc[i][3] = silu_f(acc[i][3] + pm.w + pg.w + b0v.w);
    }
    __syncthreads();            // everyone done reading As / Wsm

    #pragma unroll
    for (int i = 0; i < 8; i++)
        st4(As + (rg * 8 + i) * DD + cg * 4,
            make_float4(acc[i][0], acc[i][1], acc[i][2], acc[i][3]));
    load_W(Wsm, W1e);
    __syncthreads();

    float acc2[8][4] = {};
    gemm_tile(As, Wsm, rg, cg, acc2);

    float4 b1v = ld4(b1e + cg * 4);
    float4 gv  = ld4(ge  + cg * 4);
    float4 bv  = ld4(be  + cg * 4);
    #pragma unroll
    for (int i = 0; i < 8; i++) {
        float v0 = acc2[i][0] + b1v.x;
        float v1 = acc2[i][1] + b1v.y;
        float v2 = acc2[i][2] + b1v.z;
        float v3 = acc2[i][3] + b1v.w;
        float mu = warp_allred(v0 + v1 + v2 + v3) * 0.0078125f;
        v0 -= mu; v1 -= mu; v2 -= mu; v3 -= mu;
        float var = warp_allred(v0*v0 + v1*v1 + v2*v2 + v3*v3) * 0.0078125f;
        float rstd = rsqrtf(var + 1e-5f);
        float4 o;
        o.x = v0 * rstd * gv.x + bv.x;
        o.y = v1 * rstd * gv.y + bv.y;
        o.z = v2 * rstd * gv.z + bv.z;
        o.w = v3 * rstd * gv.w + bv.w;
        st4(g_efeat + (size_t)(e0 + rg * 8 + i) * DD + cg * 4, o);
    }
}

// ---------------------------------------------------------------------------
// Kernel 4: node MLP
//   agg = segment_sum(efeat, dst)      (dst sorted -> binary-searched ranges)
//   hn  = silu([grid, agg] @ Wn0 + bn0)
//   out = LayerNorm(hn@Wn1 + bn1; gn, bn) + grid
// ---------------------------------------------------------------------------
__global__ void __launch_bounds__(NTHREADS, 2)
node_kernel(const float* __restrict__ grid, const int* __restrict__ dst,
            const float* __restrict__ Wn0, const float* __restrict__ bn0,
            const float* __restrict__ Wn1, const float* __restrict__ bn1,
            const float* __restrict__ gn, const float* __restrict__ bn,
            float* __restrict__ out) {
    extern __shared__ float sm[];
    float* As  = sm;
    float* Wsm = sm + TM * DD;
    int* sLo = (int*)(sm + TM * DD + DD * DD);
    int* sHi = sLo + TM;

    int n0 = blockIdx.x * TM;

    // per-node edge ranges via lower_bound on the sorted dst index
    if (threadIdx.x < TM) {
        int n = n0 + (int)threadIdx.x;
        int lo = 0, hi = N_EDGES;
        while (lo < hi) { int m = (lo + hi) >> 1; if (dst[m] <  n) lo = m + 1; else hi = m; }
        sLo[threadIdx.x] = lo;
        int lo2 = lo, hi2 = N_EDGES;
        while (lo2 < hi2) { int m = (lo2 + hi2) >> 1; if (dst[m] <= n) lo2 = m + 1; else hi2 = m; }
        sHi[threadIdx.x] = lo2;
    }

    // pass 1: grid half of the concat, Wn0 rows [0,128)
    load_A(As, grid + (size_t)n0 * DD, TM);
    load_W(Wsm, Wn0);
    __syncthreads();

    int cg = threadIdx.x & 31, rg = threadIdx.x >> 5;
    float acc[8][4] = {};
    gemm_tile(As, Wsm, rg, cg, acc);
    __syncthreads();

    // pass 2: aggregate efeat into As, Wn0 rows [128,256)
    #pragma unroll
    for (int i = 0; i < 8; i++) {
        int r = rg * 8 + i;
        int lo = sLo[r], hi = sHi[r];
        float4 s = make_float4(0.f, 0.f, 0.f, 0.f);
        for (int e = lo; e < hi; e++) {
            float4 v = ld4(g_efeat + (size_t)e * DD + cg * 4);
            s.x += v.x; s.y += v.y; s.z += v.z; s.w += v.w;
        }
        st4(As + r * DD + cg * 4, s);
    }
    load_W(Wsm, Wn0 + (size_t)DD * DD);
    __syncthreads();

    gemm_tile(As, Wsm, rg, cg, acc);   // accumulate onto grid-half partials

    float4 bn0v = ld4(bn0 + cg * 4);
    #pragma unroll
    for (int i = 0; i < 8; i++) {
        acc[i][0] = silu_f(acc[i][0] + bn0v.x);
        acc[i][1] = silu_f(acc[i][1] + bn0v.y);
        acc[i][2] = silu_f(acc[i][2] + bn0v.z);
        acc[i][3] = silu_f(acc[i][3] + bn0v.w);
    }
    __syncthreads();

    #pragma unroll
    for (int i = 0; i < 8; i++)
        st4(As + (rg * 8 + i) * DD + cg * 4,
            make_float4(acc[i][0], acc[i][1], acc[i][2], acc[i][3]));
    load_W(Wsm, Wn1);
    __syncthreads();

    float acc2[8][4] = {};
    gemm_tile(As, Wsm, rg, cg, acc2);

    float4 b1v = ld4(bn1 + cg * 4);
    float4 gv  = ld4(gn  + cg * 4);
    float4 bv  = ld4(bn  + cg * 4);
    #pragma unroll
    for (int i = 0; i < 8; i++) {
        int n = n0 + rg * 8 + i;
        float v0 = acc2[i][0] + b1v.x;
        float v1 = acc2[i][1] + b1v.y;
        float v2 = acc2[i][2] + b1v.z;
        float v3 = acc2[i][3] + b1v.w;
        float mu = warp_allred(v0 + v1 + v2 + v3) * 0.0078125f;
        v0 -= mu; v1 -= mu; v2 -= mu; v3 -= mu;
        float var = warp_allred(v0*v0 + v1*v1 + v2*v2 + v3*v3) * 0.0078125f;
        float rstd = rsqrtf(var + 1e-5f);
        float4 gr = ld4(grid + (size_t)n * DD + cg * 4);
        float4 o;
        o.x = v0 * rstd * gv.x + bv.x + gr.x;
        o.y = v1 * rstd * gv.y + bv.y + gr.y;
        o.z = v2 * rstd * gv.z + bv.z + gr.z;
        o.w = v3 * rstd * gv.w + bv.w + gr.w;
        st4(out + (size_t)n * DD + cg * 4, o);
    }
}

// ---------------------------------------------------------------------------
// Launch
// ---------------------------------------------------------------------------
extern "C" void kernel_launch(void* const* d_in, const int* in_sizes, int n_in,
                              void* d_out, int out_size) {
    (void)in_sizes; (void)n_in; (void)out_size;

    const float* m2g  = (const float*)d_in[0];
    const float* grid = (const float*)d_in[1];
    const float* mesh = (const float*)d_in[2];
    const int*   src  = (const int*)  d_in[3];
    const int*   dst  = (const int*)  d_in[4];
    const float* We   = (const float*)d_in[5];
    const float* Ws   = (const float*)d_in[6];
    const float* Wd   = (const float*)d_in[7];
    const float* b0   = (const float*)d_in[8];
    const float* W1e  = (const float*)d_in[9];
    const float* b1e  = (const float*)d_in[10];
    const float* ge   = (const float*)d_in[11];
    const float* be   = (const float*)d_in[12];
    const float* Wn0  = (const float*)d_in[13];
    const float* bn0  = (const float*)d_in[14];
    const float* Wn1  = (const float*)d_in[15];
    const float* bn1  = (const float*)d_in[16];
    const float* gn   = (const float*)d_in[17];
    const float* bn   = (const float*)d_in[18];
    float* out = (float*)d_out;

    const int SMEM = (TM * DD + DD * DD) * (int)sizeof(float) + 2 * TM * (int)sizeof(int);

    cudaFuncSetAttribute(proj_kernel, cudaFuncAttributeMaxDynamicSharedMemorySize, SMEM);
    cudaFuncSetAttribute(edge_kernel, cudaFuncAttributeMaxDynamicSharedMemorySize, SMEM);
    cudaFuncSetAttribute(node_kernel, cudaFuncAttributeMaxDynamicSharedMemorySize, SMEM);

    void *pm = nullptr, *pg = nullptr;
    cudaGetSymbolAddress(&pm, g_Pmesh);
    cudaGetSymbolAddress(&pg, g_Pgrid);

    proj_kernel<<<(N_MESH + TM - 1) / TM, NTHREADS, SMEM>>>(mesh, Ws, (float*)pm, N_MESH);
    proj_kernel<<<N_GRIDN / TM,            NTHREADS, SMEM>>>(grid, Wd, (float*)pg, N_GRIDN);
    edge_kernel<<<N_EDGES / TM, NTHREADS, SMEM>>>(m2g, src, dst, We, W1e, b0, b1e, ge, be);
    node_kernel<<<N_GRIDN / TM, NTHREADS, SMEM>>>(grid, dst, Wn0, bn0, Wn1, bn1, gn, bn, out);
}

// round 9
// speedup vs baseline: 1.0020x; 1.0006x over previous
#include <cuda_runtime.h>
#include <cuda_bf16.h>

// Problem constants
#define DD 128            // feature dim D == H
#define TM 64             // rows per CTA tile
#define NTHREADS 256
#define N_MESH  40962
#define N_GRIDN 200000
#define N_EDGES 600000

// ---------------------------------------------------------------------------
// Scratch buffers (static __device__ arrays — allocation-free per the rules)
// ---------------------------------------------------------------------------
__device__ __align__(16) float g_Pmesh[(size_t)N_MESH  * DD];   //  21.0 MB
__device__ __align__(16) float g_Pgrid[(size_t)N_GRIDN * DD];   // 102.4 MB
__device__ __align__(16) float g_efeat[(size_t)N_EDGES * DD];   // 307.2 MB

// ---------------------------------------------------------------------------
// Helpers
// ---------------------------------------------------------------------------
__device__ __forceinline__ float4 ld4(const float* p) {
    return *reinterpret_cast<const float4*>(p);
}
__device__ __forceinline__ void st4(float* p, float4 v) {
    *reinterpret_cast<float4*>(p) = v;
}
__device__ __forceinline__ float warp_allred(float v) {
    #pragma unroll
    for (int o = 16; o > 0; o >>= 1) v += __shfl_xor_sync(0xffffffffu, v, o);
    return v;
}
__device__ __forceinline__ float silu_f(float x) {
    return x / (1.0f + __expf(-x));
}

// Load a TM x 128 A-tile into shared memory (float4, fully coalesced).
__device__ __forceinline__ void load_A(float* As, const float* gA, int rows_valid) {
    #pragma unroll
    for (int t = threadIdx.x; t < TM * 32; t += NTHREADS) {
        int r = t >> 5;
        int c = (t & 31) * 4;
        float4 v = make_float4(0.f, 0.f, 0.f, 0.f);
        if (r < rows_valid) v = ld4(gA + (size_t)r * DD + c);
        st4(As + r * DD + c, v);
    }
}

// Load a 128 x 128 weight tile into shared memory.
__device__ __forceinline__ void load_W(float* Wsm, const float* gW) {
    #pragma unroll
    for (int t = threadIdx.x; t < DD * 32; t += NTHREADS) {
        int r = t >> 5;
        int c = (t & 31) * 4;
        st4(Wsm + r * DD + c, ld4(gW + (size_t)r * DD + c));
    }
}

// Register-tiled GEMM: acc[i][c] += sum_k As[rg*8+i][k] * Wsm[k][cg*4+c]
// 256 threads: rg = tid>>5 (8 row groups of 8 rows), cg = tid&31 (32 col
// groups of 4 cols). A reads are warp-broadcast, W reads are conflict-free
// float4 across the 512B row.
__device__ __forceinline__ void gemm_tile(const float* __restrict__ As,
                                          const float* __restrict__ Wsm,
                                          int rg, int cg, float acc[8][4]) {
    const float* arow = As + rg * 8 * DD;
    const float* wcol = Wsm + cg * 4;
    #pragma unroll 2
    for (int k = 0; k < DD; k += 4) {
        float4 w0 = ld4(wcol + (k + 0) * DD);
        float4 w1 = ld4(wcol + (k + 1) * DD);
        float4 w2 = ld4(wcol + (k + 2) * DD);
        float4 w3 = ld4(wcol + (k + 3) * DD);
        #pragma unroll
        for (int i = 0; i < 8; i++) {
            float4 a = ld4(arow + i * DD + k);
            acc[i][0] += a.x * w0.x; acc[i][0] += a.y * w1.x;
            acc[i][0] += a.z * w2.x; acc[i][0] += a.w * w3.x;
            acc[i][1] += a.x * w0.y; acc[i][1] += a.y * w1.y;
            acc[i][1] += a.z * w2.y; acc[i][1] += a.w * w3.y;
            acc[i][2] += a.x * w0.z; acc[i][2] += a.y * w1.z;
            acc[i][2] += a.z * w2.z; acc[i][2] += a.w * w3.z;
            acc[i][3] += a.x * w0.w; acc[i][3] += a.y * w1.w;
            acc[i][3] += a.z * w2.w; acc[i][3] += a.w * w3.w;
        }
    }
}

// ---------------------------------------------------------------------------
// Kernel 1/2: C[M,128] = A[M,128] @ W[128,128]   (no bias)
// ---------------------------------------------------------------------------
__global__ void __launch_bounds__(NTHREADS, 2)
proj_kernel(const float* __restrict__ A, const float* __restrict__ W,
            float* __restrict__ C, int M) {
    extern __shared__ float sm[];
    float* As  = sm;
    float* Wsm = sm + TM * DD;

    int m0 = blockIdx.x * TM;
    int rv = M - m0; if (rv > TM) rv = TM;

    load_A(As, A + (size_t)m0 * DD, rv);
    load_W(Wsm, W);
    __syncthreads();

    int cg = threadIdx.x & 31, rg = threadIdx.x >> 5;
    float acc[8][4] = {};
    gemm_tile(As, Wsm, rg, cg, acc);

    #pragma unroll
    for (int i = 0; i < 8; i++) {
        int r = rg * 8 + i;
        if (r < rv) {
            float4 v = make_float4(acc[i][0], acc[i][1], acc[i][2], acc[i][3]);
            st4(C + (size_t)(m0 + r) * DD + cg * 4, v);
        }
    }
}

// ---------------------------------------------------------------------------
// Kernel 3: edge TMLP
//   h     = silu(m2g@We + Pmesh[src] + Pgrid[dst] + b0)
//   efeat = LayerNorm(h@W1e + b1e; ge, be)          -> g_efeat
// ---------------------------------------------------------------------------
__global__ void __launch_bounds__(NTHREADS, 2)
edge_kernel(const float* __restrict__ m2g,
            const int* __restrict__ src, const int* __restrict__ dst,
            const float* __restrict__ We, const float* __restrict__ W1e,
            const float* __restrict__ b0, const float* __restrict__ b1e,
            const float* __restrict__ ge, const float* __restrict__ be) {
    extern __shared__ float sm[];
    float* As  = sm;
    float* Wsm = sm + TM * DD;

    int e0 = blockIdx.x * TM;
    load_A(As, m2g + (size_t)e0 * DD, TM);
    load_W(Wsm, We);
    __syncthreads();

    int cg = threadIdx.x & 31, rg = threadIdx.x >> 5;
    float acc[8][4] = {};
    gemm_tile(As, Wsm, rg, cg, acc);

    // epilogue 1: gathers + bias + silu (no shared-mem access)
    float4 b0v = ld4(b0 + cg * 4);
    #pragma unroll
    for (int i = 0; i < 8; i++) {
        int e = e0 + rg * 8 + i;
        int s = __ldg(src + e);
        int d = __ldg(dst + e);
        float4 pm = ld4(g_Pmesh + (size_t)s * DD + cg * 4);
        float4 pg = ld4(g_Pgrid + (size_t)d * DD + cg * 4);
        acc[i][0] = silu_f(acc[i][0] + pm.x + pg.x + b0v.x);
        acc[i][1] = silu_f(acc[i][1] + pm.y + pg.y + b0v.y);
        acc[i][2] = silu_f(acc[i][2] + pm.z + pg.z + b0v.z);
        acc[i][3] = silu_f(acc[i][3] + pm.w + pg.w + b0v.w);
    }
    __syncthreads();            // everyone done reading As / Wsm

    #pragma unroll
    for (int i = 0; i < 8; i++)
        st4(As + (rg * 8 + i) * DD + cg * 4,
            make_float4(acc[i][0], acc[i][1], acc[i][2], acc[i][3]));
    load_W(Wsm, W1e);
    __syncthreads();

    float acc2[8][4] = {};
    gemm_tile(As, Wsm, rg, cg, acc2);

    float4 b1v = ld4(b1e + cg * 4);
    float4 gv  = ld4(ge  + cg * 4);
    float4 bv  = ld4(be  + cg * 4);
    #pragma unroll
    for (int i = 0; i < 8; i++) {
        float v0 = acc2[i][0] + b1v.x;
        float v1 = acc2[i][1] + b1v.y;
        float v2 = acc2[i][2] + b1v.z;
        float v3 = acc2[i][3] + b1v.w;
        float mu = warp_allred(v0 + v1 + v2 + v3) * 0.0078125f;
        v0 -= mu; v1 -= mu; v2 -= mu; v3 -= mu;
        float var = warp_allred(v0*v0 + v1*v1 + v2*v2 + v3*v3) * 0.0078125f;
        float rstd = rsqrtf(var + 1e-5f);
        float4 o;
        o.x = v0 * rstd * gv.x + bv.x;
        o.y = v1 * rstd * gv.y + bv.y;
        o.z = v2 * rstd * gv.z + bv.z;
        o.w = v3 * rstd * gv.w + bv.w;
        st4(g_efeat + (size_t)(e0 + rg * 8 + i) * DD + cg * 4, o);
    }
}

// ---------------------------------------------------------------------------
// Kernel 4: node MLP
//   agg = segment_sum(efeat, dst)      (dst sorted -> binary-searched ranges)
//   hn  = silu([grid, agg] @ Wn0 + bn0)
//   out = LayerNorm(hn@Wn1 + bn1; gn, bn) + grid
// ---------------------------------------------------------------------------
__global__ void __launch_bounds__(NTHREADS, 2)
node_kernel(const float* __restrict__ grid, const int* __restrict__ dst,
            const float* __restrict__ Wn0, const float* __restrict__ bn0,
            const float* __restrict__ Wn1, const float* __restrict__ bn1,
            const float* __restrict__ gn, const float* __restrict__ bn,
            float* __restrict__ out) {
    extern __shared__ float sm[];
    float* As  = sm;
    float* Wsm = sm + TM * DD;
    int* sLo = (int*)(sm + TM * DD + DD * DD);
    int* sHi = sLo + TM;

    int n0 = blockIdx.x * TM;

    // per-node edge ranges via lower_bound on the sorted dst index
    if (threadIdx.x < TM) {
        int n = n0 + (int)threadIdx.x;
        int lo = 0, hi = N_EDGES;
        while (lo < hi) { int m = (lo + hi) >> 1; if (dst[m] <  n) lo = m + 1; else hi = m; }
        sLo[threadIdx.x] = lo;
        int lo2 = lo, hi2 = N_EDGES;
        while (lo2 < hi2) { int m = (lo2 + hi2) >> 1; if (dst[m] <= n) lo2 = m + 1; else hi2 = m; }
        sHi[threadIdx.x] = lo2;
    }

    // pass 1: grid half of the concat, Wn0 rows [0,128)
    load_A(As, grid + (size_t)n0 * DD, TM);
    load_W(Wsm, Wn0);
    __syncthreads();

    int cg = threadIdx.x & 31, rg = threadIdx.x >> 5;
    float acc[8][4] = {};
    gemm_tile(As, Wsm, rg, cg, acc);
    __syncthreads();

    // pass 2: aggregate efeat into As, Wn0 rows [128,256)
    #pragma unroll
    for (int i = 0; i < 8; i++) {
        int r = rg * 8 + i;
        int lo = sLo[r], hi = sHi[r];
        float4 s = make_float4(0.f, 0.f, 0.f, 0.f);
        for (int e = lo; e < hi; e++) {
            float4 v = ld4(g_efeat + (size_t)e * DD + cg * 4);
            s.x += v.x; s.y += v.y; s.z += v.z; s.w += v.w;
        }
        st4(As + r * DD + cg * 4, s);
    }
    load_W(Wsm, Wn0 + (size_t)DD * DD);
    __syncthreads();

    gemm_tile(As, Wsm, rg, cg, acc);   // accumulate onto grid-half partials

    float4 bn0v = ld4(bn0 + cg * 4);
    #pragma unroll
    for (int i = 0; i < 8; i++) {
        acc[i][0] = silu_f(acc[i][0] + bn0v.x);
        acc[i][1] = silu_f(acc[i][1] + bn0v.y);
        acc[i][2] = silu_f(acc[i][2] + bn0v.z);
        acc[i][3] = silu_f(acc[i][3] + bn0v.w);
    }
    __syncthreads();

    #pragma unroll
    for (int i = 0; i < 8; i++)
        st4(As + (rg * 8 + i) * DD + cg * 4,
            make_float4(acc[i][0], acc[i][1], acc[i][2], acc[i][3]));
    load_W(Wsm, Wn1);
    __syncthreads();

    float acc2[8][4] = {};
    gemm_tile(As, Wsm, rg, cg, acc2);

    float4 b1v = ld4(bn1 + cg * 4);
    float4 gv  = ld4(gn  + cg * 4);
    float4 bv  = ld4(bn  + cg * 4);
    #pragma unroll
    for (int i = 0; i < 8; i++) {
        int n = n0 + rg * 8 + i;
        float v0 = acc2[i][0] + b1v.x;
        float v1 = acc2[i][1] + b1v.y;
        float v2 = acc2[i][2] + b1v.z;
        float v3 = acc2[i][3] + b1v.w;
        float mu = warp_allred(v0 + v1 + v2 + v3) * 0.0078125f;
        v0 -= mu; v1 -= mu; v2 -= mu; v3 -= mu;
        float var = warp_allred(v0*v0 + v1*v1 + v2*v2 + v3*v3) * 0.0078125f;
        float rstd = rsqrtf(var + 1e-5f);
        float4 gr = ld4(grid + (size_t)n * DD + cg * 4);
        float4 o;
        o.x = v0 * rstd * gv.x + bv.x + gr.x;
        o.y = v1 * rstd * gv.y + bv.y + gr.y;
        o.z = v2 * rstd * gv.z + bv.z + gr.z;
        o.w = v3 * rstd * gv.w + bv.w + gr.w;
        st4(out + (size_t)n * DD + cg * 4, o);
    }
}

// ---------------------------------------------------------------------------
// Launch
// ---------------------------------------------------------------------------
extern "C" void kernel_launch(void* const* d_in, const int* in_sizes, int n_in,
                              void* d_out, int out_size) {
    (void)in_sizes; (void)n_in; (void)out_size;

    const float* m2g  = (const float*)d_in[0];
    const float* grid = (const float*)d_in[1];
    const float* mesh = (const float*)d_in[2];
    const int*   src  = (const int*)  d_in[3];
    const int*   dst  = (const int*)  d_in[4];
    const float* We   = (const float*)d_in[5];
    const float* Ws   = (const float*)d_in[6];
    const float* Wd   = (const float*)d_in[7];
    const float* b0   = (const float*)d_in[8];
    const float* W1e  = (const float*)d_in[9];
    const float* b1e  = (const float*)d_in[10];
    const float* ge   = (const float*)d_in[11];
    const float* be   = (const float*)d_in[12];
    const float* Wn0  = (const float*)d_in[13];
    const float* bn0  = (const float*)d_in[14];
    const float* Wn1  = (const float*)d_in[15];
    const float* bn1  = (const float*)d_in[16];
    const float* gn   = (const float*)d_in[17];
    const float* bn   = (const float*)d_in[18];
    float* out = (float*)d_out;

    const int SMEM = (TM * DD + DD * DD) * (int)sizeof(float) + 2 * TM * (int)sizeof(int);

    cudaFuncSetAttribute(proj_kernel, cudaFuncAttributeMaxDynamicSharedMemorySize, SMEM);
    cudaFuncSetAttribute(edge_kernel, cudaFuncAttributeMaxDynamicSharedMemorySize, SMEM);
    cudaFuncSetAttribute(node_kernel, cudaFuncAttributeMaxDynamicSharedMemorySize, SMEM);

    void *pm = nullptr, *pg = nullptr;
    cudaGetSymbolAddress(&pm, g_Pmesh);
    cudaGetSymbolAddress(&pg, g_Pgrid);

    proj_kernel<<<(N_MESH + TM - 1) / TM, NTHREADS, SMEM>>>(mesh, Ws, (float*)pm, N_MESH);
    proj_kernel<<<N_GRIDN / TM,            NTHREADS, SMEM>>>(grid, Wd, (float*)pg, N_GRIDN);
    edge_kernel<<<N_EDGES / TM, NTHREADS, SMEM>>>(m2g, src, dst, We, W1e, b0, b1e, ge, be);
    node_kernel<<<N_GRIDN / TM, NTHREADS, SMEM>>>(grid, dst, Wn0, bn0, Wn1, bn1, gn, bn, out);
}